// round 13
// baseline (speedup 1.0000x reference)
#include <cuda_runtime.h>
#include <math.h>

#define SC 64
#define VC 32
#define DIMF 160
#define NB 64
#define TBL 4096
#define CUTOFF_F 5.0f
#define TILE_N 32       // nodes per finalize block
#define SAS 68          // sA row stride (floats): tn offsets 16B-distinct mod 128B
#define SVS 100         // sv row stride (floats): same property

__device__ float g_table[TBL];
__device__ double g_ewsum;

// Fused: warp-per-entry table build + grid-stride zeroing of the output
// accumulator. Launched WIDE (2560 blocks); table lives in first 512 blocks.
__global__ void k_table_zero(const float* __restrict__ centers,
                             const float* __restrict__ widths,
                             const float* __restrict__ pw,
                             const float* __restrict__ pb,
                             float4* __restrict__ outz, int nq) {
    int gt = blockIdx.x * blockDim.x + threadIdx.x;
    if (gt == 0) g_ewsum = 0.0;

    int entry = gt >> 5;
    int lane = gt & 31;
    if (entry < TBL) {
        float d = CUTOFF_F * (float)entry / (float)(TBL - 1);
        float z0 = (d - centers[lane]) / widths[lane];
        float z1 = (d - centers[lane + 32]) / widths[lane + 32];
        float v = expf(-0.5f * z0 * z0) * pw[lane]
                + expf(-0.5f * z1 * z1) * pw[lane + 32];
#pragma unroll
        for (int o = 16; o > 0; o >>= 1) v += __shfl_down_sync(0xffffffffu, v, o);
        if (lane == 0) {
            float cut = 0.5f * (cosf(3.14159265358979323846f * d / CUTOFF_F) + 1.0f);
            float t = v * cut + pb[0];
            g_table[entry] = 1.0f / (1.0f + expf(-t));
        }
    }

    const float4 z4 = make_float4(0.f, 0.f, 0.f, 0.f);
    int stride = gridDim.x * blockDim.x;
    for (int i = gt; i < nq; i += stride) outz[i] = z4;
}

// Scatter-add raw x[src] rows (40 float4) into out[dst], with the per-edge
// weight computation fused in (warp 0; overlapped with LTS-bound RED traffic).
__global__ void k_scatter(const int* __restrict__ ei,
                          const float* __restrict__ x,
                          const float* __restrict__ pos,
                          float* __restrict__ out, int E) {
    __shared__ int ss[32], sd[32];
    int base = blockIdx.x * 32;
    int t = threadIdx.x;
    if (t < 32) {
        int e = base + t;
        ss[t] = (e < E) ? ei[e] : 0;
    } else if (t < 64) {
        int e = base + t - 32;
        sd[t - 32] = (e < E) ? ei[E + e] : 0;
    }
    __syncthreads();

    if (t < 32) {
        float v = 0.f;
        int e = base + t;
        if (e < E) {
            int s = ss[t], d = sd[t];
            float dx = pos[3*s+0] - pos[3*d+0];
            float dy = pos[3*s+1] - pos[3*d+1];
            float dz = pos[3*s+2] - pos[3*d+2];
            float dist = sqrtf(dx*dx + dy*dy + dz*dz);
            float u = fminf(dist, CUTOFF_F) * ((float)(TBL - 1) / CUTOFF_F);
            int i0 = (int)u;
            if (i0 > TBL - 2) i0 = TBL - 2;
            float f = u - (float)i0;
            float t0 = g_table[i0];
            float t1 = g_table[i0 + 1];
            v = t0 + f * (t1 - t0);
        }
#pragma unroll
        for (int o = 16; o > 0; o >>= 1) v += __shfl_down_sync(0xffffffffu, v, o);
        if (t == 0) atomicAdd(&g_ewsum, (double)v);
    }

#pragma unroll
    for (int it = 0; it < 5; it++) {
        int j = t + it * 256;          // 0..1279 = 32 edges * 40 float4
        int el = j / 40;
        int k = j - el * 40;
        if (base + el >= E) continue;
        float4 v = *reinterpret_cast<const float4*>(x + (size_t)ss[el] * DIMF + k * 4);
        float* dp = out + (size_t)sd[el] * DIMF + k * 4;
        asm volatile("red.global.add.v4.f32 [%0], {%1, %2, %3, %4};"
                     :: "l"(dp), "f"(v.x), "f"(v.y), "f"(v.z), "f"(v.w)
                     : "memory");
    }
}

// Tiled finalize: 32 nodes/block. Scalar channels staged in sA[tn][64];
// vector channels staged TRANSPOSED in sv[tn][j][c] so the vector GEMM
// loads activations as float4 over c (24 LDS.128 vs 96 LDS.32 + 32 LDS.128).
__global__ void __launch_bounds__(256, 5) k_finalize(
        float* __restrict__ out,
        const float* __restrict__ W0,
        const float* __restrict__ W1,
        const float* __restrict__ gamma,
        const float* __restrict__ beta,
        int N, int E) {
    __shared__ float sA[TILE_N * SAS];     // scalar channels [tn][0..63]
    __shared__ float sv[TILE_N * SVS];     // vector transposed [tn][j*32 + c]
    __shared__ float W0sh[SC][SC];
    __shared__ float W1sh[VC][VC];

    int t  = threadIdx.x;
    int tn = t >> 3;
    int tc = t & 7;
    int base = blockIdx.x * TILE_N;
    int n = base + tn;

    for (int i = t; i < SC * SC; i += 256) W0sh[i >> 6][i & 63] = W0[i];
    for (int i = t; i < VC * VC; i += 256) W1sh[i >> 5][i & 31] = W1[i];

    // Stage 32 rows x 40 float4, splitting scalar (c4<16) / vector (transposed)
    for (int j = t; j < TILE_N * (DIMF / 4); j += 256) {
        int r  = j / 40;
        int c4 = j - r * 40;
        float4 v = make_float4(0.f, 0.f, 0.f, 0.f);
        int nr = base + r;
        if (nr < N) v = *reinterpret_cast<const float4*>(out + (size_t)nr * DIMF + c4 * 4);
        if (c4 < 16) {
            *reinterpret_cast<float4*>(&sA[r * SAS + c4 * 4]) = v;
        } else {
            int ch0 = c4 * 4 - SC;            // 0..95, ch = 3c + jj
            float vv[4] = {v.x, v.y, v.z, v.w};
#pragma unroll
            for (int q = 0; q < 4; q++) {
                int ch = ch0 + q;
                int c  = ch / 3;
                int jj = ch - 3 * c;
                sv[r * SVS + jj * VC + c] = vv[q];
            }
        }
    }

    float ew  = (float)(g_ewsum / (double)E);
    float ews = ew * 0.125f;
    float ewv = ew * 0.17677669529663689f;
    float4 gl = *reinterpret_cast<const float4*>(gamma + tc * 4);
    float4 gh = *reinterpret_cast<const float4*>(gamma + 32 + tc * 4);
    float4 bl = *reinterpret_cast<const float4*>(beta + tc * 4);
    float4 bh = *reinterpret_cast<const float4*>(beta + 32 + tc * 4);

    __syncthreads();

    // ---- scalar path: 8 accumulators ----
    float as[8];
#pragma unroll
    for (int q = 0; q < 8; q++) as[q] = 0.f;
#pragma unroll
    for (int k = 0; k < SC; k += 4) {
        float4 a4 = *reinterpret_cast<const float4*>(&sA[tn * SAS + k]);
        float av[4] = {a4.x, a4.y, a4.z, a4.w};
#pragma unroll
        for (int kk = 0; kk < 4; kk++) {
            float4 wl = *reinterpret_cast<const float4*>(&W0sh[k + kk][tc * 4]);
            float4 wh = *reinterpret_cast<const float4*>(&W0sh[k + kk][32 + tc * 4]);
            float a = av[kk];
            as[0] = fmaf(a, wl.x, as[0]);
            as[1] = fmaf(a, wl.y, as[1]);
            as[2] = fmaf(a, wl.z, as[2]);
            as[3] = fmaf(a, wl.w, as[3]);
            as[4] = fmaf(a, wh.x, as[4]);
            as[5] = fmaf(a, wh.y, as[5]);
            as[6] = fmaf(a, wh.z, as[6]);
            as[7] = fmaf(a, wh.w, as[7]);
        }
    }

    // ---- vector path: avv[3q+j] = sum_c sv[tn][j][c] * W1[c][4tc+q] ----
    float avv[12];
#pragma unroll
    for (int q = 0; q < 12; q++) avv[q] = 0.f;
#pragma unroll
    for (int i = 0; i < VC / 4; i++) {
        float4 a0 = *reinterpret_cast<const float4*>(&sv[tn * SVS + 0 * VC + 4 * i]);
        float4 a1 = *reinterpret_cast<const float4*>(&sv[tn * SVS + 1 * VC + 4 * i]);
        float4 a2 = *reinterpret_cast<const float4*>(&sv[tn * SVS + 2 * VC + 4 * i]);
        float a0v[4] = {a0.x, a0.y, a0.z, a0.w};
        float a1v[4] = {a1.x, a1.y, a1.z, a1.w};
        float a2v[4] = {a2.x, a2.y, a2.z, a2.w};
#pragma unroll
        for (int kk = 0; kk < 4; kk++) {
            float4 w = *reinterpret_cast<const float4*>(&W1sh[4 * i + kk][tc * 4]);
            avv[0]  = fmaf(a0v[kk], w.x, avv[0]);
            avv[1]  = fmaf(a1v[kk], w.x, avv[1]);
            avv[2]  = fmaf(a2v[kk], w.x, avv[2]);
            avv[3]  = fmaf(a0v[kk], w.y, avv[3]);
            avv[4]  = fmaf(a1v[kk], w.y, avv[4]);
            avv[5]  = fmaf(a2v[kk], w.y, avv[5]);
            avv[6]  = fmaf(a0v[kk], w.z, avv[6]);
            avv[7]  = fmaf(a1v[kk], w.z, avv[7]);
            avv[8]  = fmaf(a2v[kk], w.z, avv[8]);
            avv[9]  = fmaf(a0v[kk], w.w, avv[9]);
            avv[10] = fmaf(a1v[kk], w.w, avv[10]);
            avv[11] = fmaf(a2v[kk], w.w, avv[11]);
        }
    }

    // ---- scale + LN stats over the 8 lanes sharing this tn ----
    float s1 = 0.f, s2 = 0.f;
#pragma unroll
    for (int q = 0; q < 8; q++) {
        as[q] *= ews;
        s1 += as[q];
        s2 += as[q] * as[q];
    }
#pragma unroll
    for (int o = 1; o < 8; o <<= 1) {
        s1 += __shfl_xor_sync(0xffffffffu, s1, o);
        s2 += __shfl_xor_sync(0xffffffffu, s2, o);
    }
    float mu  = s1 * (1.0f / SC);
    float var = s2 * (1.0f / SC) - mu * mu;
    float rstd = rsqrtf(var + 1e-5f);

    if (n < N) {
        float* orow = out + (size_t)n * DIMF;
        float x0 = (as[0] - mu) * rstd * gl.x + bl.x;
        float x1 = (as[1] - mu) * rstd * gl.y + bl.y;
        float x2 = (as[2] - mu) * rstd * gl.z + bl.z;
        float x3 = (as[3] - mu) * rstd * gl.w + bl.w;
        float4 r0 = make_float4(x0 / (1.f + expf(-x0)), x1 / (1.f + expf(-x1)),
                                x2 / (1.f + expf(-x2)), x3 / (1.f + expf(-x3)));
        float y0 = (as[4] - mu) * rstd * gh.x + bh.x;
        float y1 = (as[5] - mu) * rstd * gh.y + bh.y;
        float y2 = (as[6] - mu) * rstd * gh.z + bh.z;
        float y3 = (as[7] - mu) * rstd * gh.w + bh.w;
        float4 r1 = make_float4(y0 / (1.f + expf(-y0)), y1 / (1.f + expf(-y1)),
                                y2 / (1.f + expf(-y2)), y3 / (1.f + expf(-y3)));
        *reinterpret_cast<float4*>(orow + tc * 4)      = r0;
        *reinterpret_cast<float4*>(orow + 32 + tc * 4) = r1;
        float* ov = orow + SC + tc * 12;
        *reinterpret_cast<float4*>(ov + 0) =
            make_float4(avv[0] * ewv, avv[1] * ewv, avv[2] * ewv, avv[3] * ewv);
        *reinterpret_cast<float4*>(ov + 4) =
            make_float4(avv[4] * ewv, avv[5] * ewv, avv[6] * ewv, avv[7] * ewv);
        *reinterpret_cast<float4*>(ov + 8) =
            make_float4(avv[8] * ewv, avv[9] * ewv, avv[10] * ewv, avv[11] * ewv);
    }
}

extern "C" void kernel_launch(void* const* d_in, const int* in_sizes, int n_in,
                              void* d_out, int out_size) {
    const float* x       = (const float*)d_in[0];
    const float* pos     = (const float*)d_in[1];
    const int*   ei      = (const int*)d_in[2];   // int32 (JAX x64 disabled)
    // d_in[3] = edge_rand: unused (rotation cancels algebraically)
    const float* W0      = (const float*)d_in[4];
    const float* W1      = (const float*)d_in[5];
    const float* centers = (const float*)d_in[6];
    const float* widths  = (const float*)d_in[7];
    const float* pw      = (const float*)d_in[8];
    const float* pb      = (const float*)d_in[9];
    const float* gamma   = (const float*)d_in[10];
    const float* beta    = (const float*)d_in[11];
    float* out = (float*)d_out;

    int N = in_sizes[0] / DIMF;
    int E = in_sizes[2] / 2;
    int nq = (N * DIMF) / 4;

    k_table_zero<<<2560, 256>>>(centers, widths, pw, pb, (float4*)out, nq);
    k_scatter<<<(E + 31) / 32, 256>>>(ei, x, pos, out, E);
    k_finalize<<<(N + TILE_N - 1) / TILE_N, 256>>>(out, W0, W1, gamma, beta, N, E);
}

// round 14
// speedup vs baseline: 1.1328x; 1.1328x over previous
#include <cuda_runtime.h>
#include <math.h>

#define SC 64
#define VC 32
#define DIMF 160
#define NB 64
#define TBL 4096
#define CUTOFF_F 5.0f
#define TILE_N 64       // nodes per finalize block (32 pairs x 8 tc = 256 thr)
#define SAS 164         // sA row stride (floats)

__device__ float g_table[TBL];
__device__ double g_ewsum;

// Fused: warp-per-entry table build + grid-stride zeroing of the output
// accumulator. Launched WIDE (2560 blocks); table lives in first 512 blocks.
__global__ void k_table_zero(const float* __restrict__ centers,
                             const float* __restrict__ widths,
                             const float* __restrict__ pw,
                             const float* __restrict__ pb,
                             float4* __restrict__ outz, int nq) {
    int gt = blockIdx.x * blockDim.x + threadIdx.x;
    if (gt == 0) g_ewsum = 0.0;

    int entry = gt >> 5;
    int lane = gt & 31;
    if (entry < TBL) {
        float d = CUTOFF_F * (float)entry / (float)(TBL - 1);
        float z0 = (d - centers[lane]) / widths[lane];
        float z1 = (d - centers[lane + 32]) / widths[lane + 32];
        float v = expf(-0.5f * z0 * z0) * pw[lane]
                + expf(-0.5f * z1 * z1) * pw[lane + 32];
#pragma unroll
        for (int o = 16; o > 0; o >>= 1) v += __shfl_down_sync(0xffffffffu, v, o);
        if (lane == 0) {
            float cut = 0.5f * (cosf(3.14159265358979323846f * d / CUTOFF_F) + 1.0f);
            float t = v * cut + pb[0];
            g_table[entry] = 1.0f / (1.0f + expf(-t));
        }
    }

    const float4 z4 = make_float4(0.f, 0.f, 0.f, 0.f);
    int stride = gridDim.x * blockDim.x;
    for (int i = gt; i < nq; i += stride) outz[i] = z4;
}

// Scatter-add raw x[src] rows (40 float4) into out[dst], with the per-edge
// weight computation fused in (warp 0; overlapped with LTS-bound RED traffic).
__global__ void k_scatter(const int* __restrict__ ei,
                          const float* __restrict__ x,
                          const float* __restrict__ pos,
                          float* __restrict__ out, int E) {
    __shared__ int ss[32], sd[32];
    int base = blockIdx.x * 32;
    int t = threadIdx.x;
    if (t < 32) {
        int e = base + t;
        ss[t] = (e < E) ? ei[e] : 0;
    } else if (t < 64) {
        int e = base + t - 32;
        sd[t - 32] = (e < E) ? ei[E + e] : 0;
    }
    __syncthreads();

    if (t < 32) {
        float v = 0.f;
        int e = base + t;
        if (e < E) {
            int s = ss[t], d = sd[t];
            float dx = pos[3*s+0] - pos[3*d+0];
            float dy = pos[3*s+1] - pos[3*d+1];
            float dz = pos[3*s+2] - pos[3*d+2];
            float dist = sqrtf(dx*dx + dy*dy + dz*dz);
            float u = fminf(dist, CUTOFF_F) * ((float)(TBL - 1) / CUTOFF_F);
            int i0 = (int)u;
            if (i0 > TBL - 2) i0 = TBL - 2;
            float f = u - (float)i0;
            float t0 = g_table[i0];
            float t1 = g_table[i0 + 1];
            v = t0 + f * (t1 - t0);
        }
#pragma unroll
        for (int o = 16; o > 0; o >>= 1) v += __shfl_down_sync(0xffffffffu, v, o);
        if (t == 0) atomicAdd(&g_ewsum, (double)v);
    }

#pragma unroll
    for (int it = 0; it < 5; it++) {
        int j = t + it * 256;          // 0..1279 = 32 edges * 40 float4
        int el = j / 40;
        int k = j - el * 40;
        if (base + el >= E) continue;
        float4 v = *reinterpret_cast<const float4*>(x + (size_t)ss[el] * DIMF + k * 4);
        float* dp = out + (size_t)sd[el] * DIMF + k * 4;
        asm volatile("red.global.add.v4.f32 [%0], {%1, %2, %3, %4};"
                     :: "l"(dp), "f"(v.x), "f"(v.y), "f"(v.z), "f"(v.w)
                     : "memory");
    }
}

// Tiled finalize, node-pair per thread: 64 nodes/block, 256 threads.
// Thread (tp = t/8, tc = t%8) computes nodes {2tp, 2tp+1} for scalar cols
// {4tc..+4, 32+4tc..+4} and vector cols 64+12tc..+12. W smem loads are
// issued once per k and feed both nodes (halves W-LDS per node).
__global__ void __launch_bounds__(256, 3) k_finalize(
        float* __restrict__ out,
        const float* __restrict__ W0,
        const float* __restrict__ W1,
        const float* __restrict__ gamma,
        const float* __restrict__ beta,
        int N, int E) {
    __shared__ float sA[TILE_N * SAS];
    __shared__ float W0sh[SC][SC];
    __shared__ float W1sh[VC][VC];

    int t  = threadIdx.x;
    int tp = t >> 3;
    int tc = t & 7;
    int base = blockIdx.x * TILE_N;
    int r0 = 2 * tp, r1 = 2 * tp + 1;

    for (int i = t; i < SC * SC; i += 256) W0sh[i >> 6][i & 63] = W0[i];
    for (int i = t; i < VC * VC; i += 256) W1sh[i >> 5][i & 31] = W1[i];

    // Stage 64 rows x 40 float4 (coalesced; 10 per thread)
    for (int j = t; j < TILE_N * (DIMF / 4); j += 256) {
        int r  = j / 40;
        int c4 = j - r * 40;
        float4 v = make_float4(0.f, 0.f, 0.f, 0.f);
        int nr = base + r;
        if (nr < N) v = *reinterpret_cast<const float4*>(out + (size_t)nr * DIMF + c4 * 4);
        *reinterpret_cast<float4*>(&sA[r * SAS + c4 * 4]) = v;
    }

    float ew  = (float)(g_ewsum / (double)E);
    float ews = ew * 0.125f;
    float ewv = ew * 0.17677669529663689f;

    __syncthreads();

    // ---- scalar path: 8 accumulators per node ----
    float as0[8], as1[8];
#pragma unroll
    for (int q = 0; q < 8; q++) { as0[q] = 0.f; as1[q] = 0.f; }
#pragma unroll
    for (int k = 0; k < SC; k += 4) {
        float4 a40 = *reinterpret_cast<const float4*>(&sA[r0 * SAS + k]);
        float4 a41 = *reinterpret_cast<const float4*>(&sA[r1 * SAS + k]);
        float av0[4] = {a40.x, a40.y, a40.z, a40.w};
        float av1[4] = {a41.x, a41.y, a41.z, a41.w};
#pragma unroll
        for (int kk = 0; kk < 4; kk++) {
            float4 wl = *reinterpret_cast<const float4*>(&W0sh[k + kk][tc * 4]);
            float4 wh = *reinterpret_cast<const float4*>(&W0sh[k + kk][32 + tc * 4]);
            float a = av0[kk], b = av1[kk];
            as0[0] = fmaf(a, wl.x, as0[0]);  as1[0] = fmaf(b, wl.x, as1[0]);
            as0[1] = fmaf(a, wl.y, as0[1]);  as1[1] = fmaf(b, wl.y, as1[1]);
            as0[2] = fmaf(a, wl.z, as0[2]);  as1[2] = fmaf(b, wl.z, as1[2]);
            as0[3] = fmaf(a, wl.w, as0[3]);  as1[3] = fmaf(b, wl.w, as1[3]);
            as0[4] = fmaf(a, wh.x, as0[4]);  as1[4] = fmaf(b, wh.x, as1[4]);
            as0[5] = fmaf(a, wh.y, as0[5]);  as1[5] = fmaf(b, wh.y, as1[5]);
            as0[6] = fmaf(a, wh.z, as0[6]);  as1[6] = fmaf(b, wh.z, as1[6]);
            as0[7] = fmaf(a, wh.w, as0[7]);  as1[7] = fmaf(b, wh.w, as1[7]);
        }
    }

    // ---- vector path: 12 accumulators per node ----
    float av0a[12], av1a[12];
#pragma unroll
    for (int q = 0; q < 12; q++) { av0a[q] = 0.f; av1a[q] = 0.f; }
#pragma unroll
    for (int c = 0; c < VC; c++) {
        float p0 = sA[r0 * SAS + SC + 3 * c + 0];
        float p1 = sA[r0 * SAS + SC + 3 * c + 1];
        float p2 = sA[r0 * SAS + SC + 3 * c + 2];
        float q0 = sA[r1 * SAS + SC + 3 * c + 0];
        float q1 = sA[r1 * SAS + SC + 3 * c + 1];
        float q2 = sA[r1 * SAS + SC + 3 * c + 2];
        float4 w = *reinterpret_cast<const float4*>(&W1sh[c][tc * 4]);
        av0a[0]  = fmaf(p0, w.x, av0a[0]);   av1a[0]  = fmaf(q0, w.x, av1a[0]);
        av0a[1]  = fmaf(p1, w.x, av0a[1]);   av1a[1]  = fmaf(q1, w.x, av1a[1]);
        av0a[2]  = fmaf(p2, w.x, av0a[2]);   av1a[2]  = fmaf(q2, w.x, av1a[2]);
        av0a[3]  = fmaf(p0, w.y, av0a[3]);   av1a[3]  = fmaf(q0, w.y, av1a[3]);
        av0a[4]  = fmaf(p1, w.y, av0a[4]);   av1a[4]  = fmaf(q1, w.y, av1a[4]);
        av0a[5]  = fmaf(p2, w.y, av0a[5]);   av1a[5]  = fmaf(q2, w.y, av1a[5]);
        av0a[6]  = fmaf(p0, w.z, av0a[6]);   av1a[6]  = fmaf(q0, w.z, av1a[6]);
        av0a[7]  = fmaf(p1, w.z, av0a[7]);   av1a[7]  = fmaf(q1, w.z, av1a[7]);
        av0a[8]  = fmaf(p2, w.z, av0a[8]);   av1a[8]  = fmaf(q2, w.z, av1a[8]);
        av0a[9]  = fmaf(p0, w.w, av0a[9]);   av1a[9]  = fmaf(q0, w.w, av1a[9]);
        av0a[10] = fmaf(p1, w.w, av0a[10]);  av1a[10] = fmaf(q1, w.w, av1a[10]);
        av0a[11] = fmaf(p2, w.w, av0a[11]);  av1a[11] = fmaf(q2, w.w, av1a[11]);
    }

    // ---- scale + LN stats (per node) over the 8 tc-lanes ----
    float s10 = 0.f, s20 = 0.f, s11 = 0.f, s21 = 0.f;
#pragma unroll
    for (int q = 0; q < 8; q++) {
        as0[q] *= ews;  s10 += as0[q];  s20 += as0[q] * as0[q];
        as1[q] *= ews;  s11 += as1[q];  s21 += as1[q] * as1[q];
    }
#pragma unroll
    for (int o = 1; o < 8; o <<= 1) {
        s10 += __shfl_xor_sync(0xffffffffu, s10, o);
        s20 += __shfl_xor_sync(0xffffffffu, s20, o);
        s11 += __shfl_xor_sync(0xffffffffu, s11, o);
        s21 += __shfl_xor_sync(0xffffffffu, s21, o);
    }
    float mu0  = s10 * (1.0f / SC);
    float var0 = s20 * (1.0f / SC) - mu0 * mu0;
    float rs0  = rsqrtf(var0 + 1e-5f);
    float mu1  = s11 * (1.0f / SC);
    float var1 = s21 * (1.0f / SC) - mu1 * mu1;
    float rs1  = rsqrtf(var1 + 1e-5f);

    // gamma/beta loaded in epilogue (keeps mainloop register pressure down)
    float4 gl = *reinterpret_cast<const float4*>(gamma + tc * 4);
    float4 gh = *reinterpret_cast<const float4*>(gamma + 32 + tc * 4);
    float4 bl = *reinterpret_cast<const float4*>(beta + tc * 4);
    float4 bh = *reinterpret_cast<const float4*>(beta + 32 + tc * 4);
    const float* gv[8] = {&gl.x, &gl.y, &gl.z, &gl.w, &gh.x, &gh.y, &gh.z, &gh.w};
    const float* bv[8] = {&bl.x, &bl.y, &bl.z, &bl.w, &bh.x, &bh.y, &bh.z, &bh.w};

#pragma unroll
    for (int nn = 0; nn < 2; nn++) {
        int n = base + 2 * tp + nn;
        if (n >= N) break;
        float mu = nn ? mu1 : mu0;
        float rs = nn ? rs1 : rs0;
        float* asv = nn ? as1 : as0;
        float* avv = nn ? av1a : av0a;
        float* orow = out + (size_t)n * DIMF;
        float o8[8];
#pragma unroll
        for (int q = 0; q < 8; q++) {
            float xln = (asv[q] - mu) * rs * (*gv[q]) + (*bv[q]);
            o8[q] = xln / (1.f + expf(-xln));
        }
        *reinterpret_cast<float4*>(orow + tc * 4) =
            make_float4(o8[0], o8[1], o8[2], o8[3]);
        *reinterpret_cast<float4*>(orow + 32 + tc * 4) =
            make_float4(o8[4], o8[5], o8[6], o8[7]);
        float* ov = orow + SC + tc * 12;
        *reinterpret_cast<float4*>(ov + 0) =
            make_float4(avv[0] * ewv, avv[1] * ewv, avv[2] * ewv, avv[3] * ewv);
        *reinterpret_cast<float4*>(ov + 4) =
            make_float4(avv[4] * ewv, avv[5] * ewv, avv[6] * ewv, avv[7] * ewv);
        *reinterpret_cast<float4*>(ov + 8) =
            make_float4(avv[8] * ewv, avv[9] * ewv, avv[10] * ewv, avv[11] * ewv);
    }
}

extern "C" void kernel_launch(void* const* d_in, const int* in_sizes, int n_in,
                              void* d_out, int out_size) {
    const float* x       = (const float*)d_in[0];
    const float* pos     = (const float*)d_in[1];
    const int*   ei      = (const int*)d_in[2];   // int32 (JAX x64 disabled)
    // d_in[3] = edge_rand: unused (rotation cancels algebraically)
    const float* W0      = (const float*)d_in[4];
    const float* W1      = (const float*)d_in[5];
    const float* centers = (const float*)d_in[6];
    const float* widths  = (const float*)d_in[7];
    const float* pw      = (const float*)d_in[8];
    const float* pb      = (const float*)d_in[9];
    const float* gamma   = (const float*)d_in[10];
    const float* beta    = (const float*)d_in[11];
    float* out = (float*)d_out;

    int N = in_sizes[0] / DIMF;
    int E = in_sizes[2] / 2;
    int nq = (N * DIMF) / 4;

    k_table_zero<<<2560, 256>>>(centers, widths, pw, pb, (float4*)out, nq);
    k_scatter<<<(E + 31) / 32, 256>>>(ei, x, pos, out, E);
    k_finalize<<<(N + TILE_N - 1) / TILE_N, 256>>>(out, W0, W1, gamma, beta, N, E);
}

// round 16
// speedup vs baseline: 1.1400x; 1.0063x over previous
#include <cuda_runtime.h>
#include <math.h>

#define SC 64
#define VC 32
#define DIMF 160
#define NB 64
#define TBL 4096
#define CUTOFF_F 5.0f
#define TILE_N 64       // nodes per finalize block (32 pairs x 8 tc = 256 thr)
#define SAS 164         // sA row stride (floats)

__device__ float g_table[TBL];
__device__ double g_ewsum;

// Fused: warp-per-entry table build + grid-stride zeroing of the output
// accumulator. Launched WIDE (2560 blocks); table lives in first 512 blocks.
__global__ void k_table_zero(const float* __restrict__ centers,
                             const float* __restrict__ widths,
                             const float* __restrict__ pw,
                             const float* __restrict__ pb,
                             float4* __restrict__ outz, int nq) {
    int gt = blockIdx.x * blockDim.x + threadIdx.x;
    if (gt == 0) g_ewsum = 0.0;

    int entry = gt >> 5;
    int lane = gt & 31;
    if (entry < TBL) {
        float d = CUTOFF_F * (float)entry / (float)(TBL - 1);
        float z0 = (d - centers[lane]) / widths[lane];
        float z1 = (d - centers[lane + 32]) / widths[lane + 32];
        float v = expf(-0.5f * z0 * z0) * pw[lane]
                + expf(-0.5f * z1 * z1) * pw[lane + 32];
#pragma unroll
        for (int o = 16; o > 0; o >>= 1) v += __shfl_down_sync(0xffffffffu, v, o);
        if (lane == 0) {
            float cut = 0.5f * (cosf(3.14159265358979323846f * d / CUTOFF_F) + 1.0f);
            float t = v * cut + pb[0];
            g_table[entry] = 1.0f / (1.0f + expf(-t));
        }
    }

    const float4 z4 = make_float4(0.f, 0.f, 0.f, 0.f);
    int stride = gridDim.x * blockDim.x;
    for (int i = gt; i < nq; i += stride) outz[i] = z4;
}

// Scatter-add raw x[src] rows (40 float4) into out[dst], with the per-edge
// weight computation fused in (warp 0; overlapped with LTS-bound RED traffic).
__global__ void k_scatter(const int* __restrict__ ei,
                          const float* __restrict__ x,
                          const float* __restrict__ pos,
                          float* __restrict__ out, int E) {
    __shared__ int ss[32], sd[32];
    int base = blockIdx.x * 32;
    int t = threadIdx.x;
    if (t < 32) {
        int e = base + t;
        ss[t] = (e < E) ? ei[e] : 0;
    } else if (t < 64) {
        int e = base + t - 32;
        sd[t - 32] = (e < E) ? ei[E + e] : 0;
    }
    __syncthreads();

    if (t < 32) {
        float v = 0.f;
        int e = base + t;
        if (e < E) {
            int s = ss[t], d = sd[t];
            float dx = pos[3*s+0] - pos[3*d+0];
            float dy = pos[3*s+1] - pos[3*d+1];
            float dz = pos[3*s+2] - pos[3*d+2];
            float dist = sqrtf(dx*dx + dy*dy + dz*dz);
            float u = fminf(dist, CUTOFF_F) * ((float)(TBL - 1) / CUTOFF_F);
            int i0 = (int)u;
            if (i0 > TBL - 2) i0 = TBL - 2;
            float f = u - (float)i0;
            float t0 = g_table[i0];
            float t1 = g_table[i0 + 1];
            v = t0 + f * (t1 - t0);
        }
#pragma unroll
        for (int o = 16; o > 0; o >>= 1) v += __shfl_down_sync(0xffffffffu, v, o);
        if (t == 0) atomicAdd(&g_ewsum, (double)v);
    }

#pragma unroll
    for (int it = 0; it < 5; it++) {
        int j = t + it * 256;          // 0..1279 = 32 edges * 40 float4
        int el = j / 40;
        int k = j - el * 40;
        if (base + el >= E) continue;
        float4 v = *reinterpret_cast<const float4*>(x + (size_t)ss[el] * DIMF + k * 4);
        float* dp = out + (size_t)sd[el] * DIMF + k * 4;
        asm volatile("red.global.add.v4.f32 [%0], {%1, %2, %3, %4};"
                     :: "l"(dp), "f"(v.x), "f"(v.y), "f"(v.z), "f"(v.w)
                     : "memory");
    }
}

// acc[3*col + j] += p_j * wv[col], col=0..3, j=0..2 (12 FMAs)
__device__ __forceinline__ void vacc(float* acc, float p0, float p1, float p2,
                                     const float4& wv) {
    acc[0]  = fmaf(p0, wv.x, acc[0]);
    acc[1]  = fmaf(p1, wv.x, acc[1]);
    acc[2]  = fmaf(p2, wv.x, acc[2]);
    acc[3]  = fmaf(p0, wv.y, acc[3]);
    acc[4]  = fmaf(p1, wv.y, acc[4]);
    acc[5]  = fmaf(p2, wv.y, acc[5]);
    acc[6]  = fmaf(p0, wv.z, acc[6]);
    acc[7]  = fmaf(p1, wv.z, acc[7]);
    acc[8]  = fmaf(p2, wv.z, acc[8]);
    acc[9]  = fmaf(p0, wv.w, acc[9]);
    acc[10] = fmaf(p1, wv.w, acc[10]);
    acc[11] = fmaf(p2, wv.w, acc[11]);
}

// Tiled finalize, node-pair per thread: 64 nodes/block, 256 threads.
// Thread (tp = t/8, tc = t%8) computes nodes {2tp, 2tp+1}.
// Vector path processes 12-channel blocks (4 c's) via 3 float4 loads/node:
// 8 iters x (6 act + 4 W) LDS.128 vs R14's 32 x (6 LDS.32 + 1 LDS.128).
__global__ void __launch_bounds__(256, 3) k_finalize(
        float* __restrict__ out,
        const float* __restrict__ W0,
        const float* __restrict__ W1,
        const float* __restrict__ gamma,
        const float* __restrict__ beta,
        int N, int E) {
    __shared__ float sA[TILE_N * SAS];
    __shared__ float W0sh[SC][SC];
    __shared__ float W1sh[VC][VC];

    int t  = threadIdx.x;
    int tp = t >> 3;
    int tc = t & 7;
    int base = blockIdx.x * TILE_N;
    int r0 = 2 * tp, r1 = 2 * tp + 1;

    for (int i = t; i < SC * SC; i += 256) W0sh[i >> 6][i & 63] = W0[i];
    for (int i = t; i < VC * VC; i += 256) W1sh[i >> 5][i & 31] = W1[i];

    for (int j = t; j < TILE_N * (DIMF / 4); j += 256) {
        int r  = j / 40;
        int c4 = j - r * 40;
        float4 v = make_float4(0.f, 0.f, 0.f, 0.f);
        int nr = base + r;
        if (nr < N) v = *reinterpret_cast<const float4*>(out + (size_t)nr * DIMF + c4 * 4);
        *reinterpret_cast<float4*>(&sA[r * SAS + c4 * 4]) = v;
    }

    float ew  = (float)(g_ewsum / (double)E);
    float ews = ew * 0.125f;
    float ewv = ew * 0.17677669529663689f;

    __syncthreads();

    // ---- scalar path: 8 accumulators per node ----
    float as0[8], as1[8];
#pragma unroll
    for (int q = 0; q < 8; q++) { as0[q] = 0.f; as1[q] = 0.f; }
#pragma unroll
    for (int k = 0; k < SC; k += 4) {
        float4 a40 = *reinterpret_cast<const float4*>(&sA[r0 * SAS + k]);
        float4 a41 = *reinterpret_cast<const float4*>(&sA[r1 * SAS + k]);
        float av0[4] = {a40.x, a40.y, a40.z, a40.w};
        float av1[4] = {a41.x, a41.y, a41.z, a41.w};
#pragma unroll
        for (int kk = 0; kk < 4; kk++) {
            float4 wl = *reinterpret_cast<const float4*>(&W0sh[k + kk][tc * 4]);
            float4 wh = *reinterpret_cast<const float4*>(&W0sh[k + kk][32 + tc * 4]);
            float a = av0[kk], b = av1[kk];
            as0[0] = fmaf(a, wl.x, as0[0]);  as1[0] = fmaf(b, wl.x, as1[0]);
            as0[1] = fmaf(a, wl.y, as0[1]);  as1[1] = fmaf(b, wl.y, as1[1]);
            as0[2] = fmaf(a, wl.z, as0[2]);  as1[2] = fmaf(b, wl.z, as1[2]);
            as0[3] = fmaf(a, wl.w, as0[3]);  as1[3] = fmaf(b, wl.w, as1[3]);
            as0[4] = fmaf(a, wh.x, as0[4]);  as1[4] = fmaf(b, wh.x, as1[4]);
            as0[5] = fmaf(a, wh.y, as0[5]);  as1[5] = fmaf(b, wh.y, as1[5]);
            as0[6] = fmaf(a, wh.z, as0[6]);  as1[6] = fmaf(b, wh.z, as1[6]);
            as0[7] = fmaf(a, wh.w, as0[7]);  as1[7] = fmaf(b, wh.w, as1[7]);
        }
    }

    // ---- vector path: 12-channel blocks, all-float4 loads ----
    // Block u covers channels 12u..12u+11 = c in {4u..4u+3}, j in {0,1,2}.
    // A=(c0j0,c0j1,c0j2,c1j0) B=(c1j1,c1j2,c2j0,c2j1) C=(c2j2,c3j0,c3j1,c3j2)
    float av0a[12], av1a[12];
#pragma unroll
    for (int q = 0; q < 12; q++) { av0a[q] = 0.f; av1a[q] = 0.f; }
#pragma unroll
    for (int u = 0; u < 8; u++) {
        const float* b0 = &sA[r0 * SAS + SC + 12 * u];
        const float* b1 = &sA[r1 * SAS + SC + 12 * u];
        float4 A0 = *reinterpret_cast<const float4*>(b0);
        float4 B0 = *reinterpret_cast<const float4*>(b0 + 4);
        float4 C0 = *reinterpret_cast<const float4*>(b0 + 8);
        float4 A1 = *reinterpret_cast<const float4*>(b1);
        float4 B1 = *reinterpret_cast<const float4*>(b1 + 4);
        float4 C1 = *reinterpret_cast<const float4*>(b1 + 8);
        float4 w0 = *reinterpret_cast<const float4*>(&W1sh[4*u+0][tc * 4]);
        float4 w1 = *reinterpret_cast<const float4*>(&W1sh[4*u+1][tc * 4]);
        float4 w2 = *reinterpret_cast<const float4*>(&W1sh[4*u+2][tc * 4]);
        float4 w3 = *reinterpret_cast<const float4*>(&W1sh[4*u+3][tc * 4]);
        vacc(av0a, A0.x, A0.y, A0.z, w0);
        vacc(av0a, A0.w, B0.x, B0.y, w1);
        vacc(av0a, B0.z, B0.w, C0.x, w2);
        vacc(av0a, C0.y, C0.z, C0.w, w3);
        vacc(av1a, A1.x, A1.y, A1.z, w0);
        vacc(av1a, A1.w, B1.x, B1.y, w1);
        vacc(av1a, B1.z, B1.w, C1.x, w2);
        vacc(av1a, C1.y, C1.z, C1.w, w3);
    }

    // ---- scale + LN stats (per node) over the 8 tc-lanes ----
    float s10 = 0.f, s20 = 0.f, s11 = 0.f, s21 = 0.f;
#pragma unroll
    for (int q = 0; q < 8; q++) {
        as0[q] *= ews;  s10 += as0[q];  s20 += as0[q] * as0[q];
        as1[q] *= ews;  s11 += as1[q];  s21 += as1[q] * as1[q];
    }
#pragma unroll
    for (int o = 1; o < 8; o <<= 1) {
        s10 += __shfl_xor_sync(0xffffffffu, s10, o);
        s20 += __shfl_xor_sync(0xffffffffu, s20, o);
        s11 += __shfl_xor_sync(0xffffffffu, s11, o);
        s21 += __shfl_xor_sync(0xffffffffu, s21, o);
    }
    float mu0  = s10 * (1.0f / SC);
    float var0 = s20 * (1.0f / SC) - mu0 * mu0;
    float rs0  = rsqrtf(var0 + 1e-5f);
    float mu1  = s11 * (1.0f / SC);
    float var1 = s21 * (1.0f / SC) - mu1 * mu1;
    float rs1  = rsqrtf(var1 + 1e-5f);

    float4 gl = *reinterpret_cast<const float4*>(gamma + tc * 4);
    float4 gh = *reinterpret_cast<const float4*>(gamma + 32 + tc * 4);
    float4 bl = *reinterpret_cast<const float4*>(beta + tc * 4);
    float4 bh = *reinterpret_cast<const float4*>(beta + 32 + tc * 4);
    float gvv[8] = {gl.x, gl.y, gl.z, gl.w, gh.x, gh.y, gh.z, gh.w};
    float bvv[8] = {bl.x, bl.y, bl.z, bl.w, bh.x, bh.y, bh.z, bh.w};

#pragma unroll
    for (int nn = 0; nn < 2; nn++) {
        int n = base + 2 * tp + nn;
        if (n >= N) break;
        float mu = nn ? mu1 : mu0;
        float rs = nn ? rs1 : rs0;
        float* asv = nn ? as1 : as0;
        float* avv = nn ? av1a : av0a;
        float* orow = out + (size_t)n * DIMF;
        float o8[8];
#pragma unroll
        for (int q = 0; q < 8; q++) {
            float xln = (asv[q] - mu) * rs * gvv[q] + bvv[q];
            o8[q] = xln / (1.f + expf(-xln));
        }
        *reinterpret_cast<float4*>(orow + tc * 4) =
            make_float4(o8[0], o8[1], o8[2], o8[3]);
        *reinterpret_cast<float4*>(orow + 32 + tc * 4) =
            make_float4(o8[4], o8[5], o8[6], o8[7]);
        float* ov = orow + SC + tc * 12;
        *reinterpret_cast<float4*>(ov + 0) =
            make_float4(avv[0] * ewv, avv[1] * ewv, avv[2] * ewv, avv[3] * ewv);
        *reinterpret_cast<float4*>(ov + 4) =
            make_float4(avv[4] * ewv, avv[5] * ewv, avv[6] * ewv, avv[7] * ewv);
        *reinterpret_cast<float4*>(ov + 8) =
            make_float4(avv[8] * ewv, avv[9] * ewv, avv[10] * ewv, avv[11] * ewv);
    }
}

extern "C" void kernel_launch(void* const* d_in, const int* in_sizes, int n_in,
                              void* d_out, int out_size) {
    const float* x       = (const float*)d_in[0];
    const float* pos     = (const float*)d_in[1];
    const int*   ei      = (const int*)d_in[2];   // int32 (JAX x64 disabled)
    // d_in[3] = edge_rand: unused (rotation cancels algebraically)
    const float* W0      = (const float*)d_in[4];
    const float* W1      = (const float*)d_in[5];
    const float* centers = (const float*)d_in[6];
    const float* widths  = (const float*)d_in[7];
    const float* pw      = (const float*)d_in[8];
    const float* pb      = (const float*)d_in[9];
    const float* gamma   = (const float*)d_in[10];
    const float* beta    = (const float*)d_in[11];
    float* out = (float*)d_out;

    int N = in_sizes[0] / DIMF;
    int E = in_sizes[2] / 2;
    int nq = (N * DIMF) / 4;

    k_table_zero<<<2560, 256>>>(centers, widths, pw, pb, (float4*)out, nq);
    k_scatter<<<(E + 31) / 32, 256>>>(ei, x, pos, out, E);
    k_finalize<<<(N + TILE_N - 1) / TILE_N, 256>>>(out, W0, W1, gamma, beta, N, E);
}

// round 17
// speedup vs baseline: 1.1603x; 1.0178x over previous
#include <cuda_runtime.h>
#include <math.h>

#define SC 64
#define VC 32
#define DIMF 160
#define NB 64
#define TBL 4096
#define CUTOFF_F 5.0f
#define TILE_N 64       // nodes per finalize block (32 pairs x 8 tc = 256 thr)
#define SAS 164         // sA row stride (floats)

__device__ float g_table[TBL];
__device__ double g_ewsum;

// Fused: warp-per-entry table build + grid-stride zeroing of the output
// accumulator. Launched WIDE (2560 blocks); table lives in first 512 blocks.
__global__ void k_table_zero(const float* __restrict__ centers,
                             const float* __restrict__ widths,
                             const float* __restrict__ pw,
                             const float* __restrict__ pb,
                             float4* __restrict__ outz, int nq) {
    int gt = blockIdx.x * blockDim.x + threadIdx.x;
    if (gt == 0) g_ewsum = 0.0;

    int entry = gt >> 5;
    int lane = gt & 31;
    if (entry < TBL) {
        float d = CUTOFF_F * (float)entry / (float)(TBL - 1);
        float z0 = (d - centers[lane]) / widths[lane];
        float z1 = (d - centers[lane + 32]) / widths[lane + 32];
        float v = expf(-0.5f * z0 * z0) * pw[lane]
                + expf(-0.5f * z1 * z1) * pw[lane + 32];
#pragma unroll
        for (int o = 16; o > 0; o >>= 1) v += __shfl_down_sync(0xffffffffu, v, o);
        if (lane == 0) {
            float cut = 0.5f * (cosf(3.14159265358979323846f * d / CUTOFF_F) + 1.0f);
            float t = v * cut + pb[0];
            g_table[entry] = 1.0f / (1.0f + expf(-t));
        }
    }

    const float4 z4 = make_float4(0.f, 0.f, 0.f, 0.f);
    int stride = gridDim.x * blockDim.x;
    for (int i = gt; i < nq; i += stride) outz[i] = z4;
}

// Scatter-add raw x[src] rows (40 float4) into out[dst], fused edge weight.
// Fast path for full 32-edge blocks: all 5 LDG.128 issued before any RED
// (MLP 5) — the guarded loop serialized each LDG->RED pair (MLP 1).
__global__ void k_scatter(const int* __restrict__ ei,
                          const float* __restrict__ x,
                          const float* __restrict__ pos,
                          float* __restrict__ out, int E) {
    __shared__ int ss[32], sd[32];
    int base = blockIdx.x * 32;
    int t = threadIdx.x;
    if (t < 32) {
        int e = base + t;
        ss[t] = (e < E) ? ei[e] : 0;
    } else if (t < 64) {
        int e = base + t - 32;
        sd[t - 32] = (e < E) ? ei[E + e] : 0;
    }
    __syncthreads();

    // Fused edge weight (warp 0 only)
    if (t < 32) {
        float v = 0.f;
        int e = base + t;
        if (e < E) {
            int s = ss[t], d = sd[t];
            float dx = pos[3*s+0] - pos[3*d+0];
            float dy = pos[3*s+1] - pos[3*d+1];
            float dz = pos[3*s+2] - pos[3*d+2];
            float dist = sqrtf(dx*dx + dy*dy + dz*dz);
            float u = fminf(dist, CUTOFF_F) * ((float)(TBL - 1) / CUTOFF_F);
            int i0 = (int)u;
            if (i0 > TBL - 2) i0 = TBL - 2;
            float f = u - (float)i0;
            float t0 = g_table[i0];
            float t1 = g_table[i0 + 1];
            v = t0 + f * (t1 - t0);
        }
#pragma unroll
        for (int o = 16; o > 0; o >>= 1) v += __shfl_down_sync(0xffffffffu, v, o);
        if (t == 0) atomicAdd(&g_ewsum, (double)v);
    }

    if (base + 32 <= E) {
        // Fast path: no guards -> gathers batched, MLP 5.
        float4 v[5];
        float* dp[5];
#pragma unroll
        for (int it = 0; it < 5; it++) {
            int j = t + it * 256;          // 0..1279 = 32 edges * 40 float4
            int el = j / 40;
            int k = j - el * 40;
            v[it] = *reinterpret_cast<const float4*>(x + (size_t)ss[el] * DIMF + k * 4);
            dp[it] = out + (size_t)sd[el] * DIMF + k * 4;
        }
#pragma unroll
        for (int it = 0; it < 5; it++) {
            asm volatile("red.global.add.v4.f32 [%0], {%1, %2, %3, %4};"
                         :: "l"(dp[it]), "f"(v[it].x), "f"(v[it].y),
                            "f"(v[it].z), "f"(v[it].w)
                         : "memory");
        }
    } else {
        // Tail path (partial block)
#pragma unroll
        for (int it = 0; it < 5; it++) {
            int j = t + it * 256;
            int el = j / 40;
            int k = j - el * 40;
            if (base + el >= E) continue;
            float4 v = *reinterpret_cast<const float4*>(x + (size_t)ss[el] * DIMF + k * 4);
            float* dp = out + (size_t)sd[el] * DIMF + k * 4;
            asm volatile("red.global.add.v4.f32 [%0], {%1, %2, %3, %4};"
                         :: "l"(dp), "f"(v.x), "f"(v.y), "f"(v.z), "f"(v.w)
                         : "memory");
        }
    }
}

// acc[3*col + j] += p_j * wv[col], col=0..3, j=0..2 (12 FMAs)
__device__ __forceinline__ void vacc(float* acc, float p0, float p1, float p2,
                                     const float4& wv) {
    acc[0]  = fmaf(p0, wv.x, acc[0]);
    acc[1]  = fmaf(p1, wv.x, acc[1]);
    acc[2]  = fmaf(p2, wv.x, acc[2]);
    acc[3]  = fmaf(p0, wv.y, acc[3]);
    acc[4]  = fmaf(p1, wv.y, acc[4]);
    acc[5]  = fmaf(p2, wv.y, acc[5]);
    acc[6]  = fmaf(p0, wv.z, acc[6]);
    acc[7]  = fmaf(p1, wv.z, acc[7]);
    acc[8]  = fmaf(p2, wv.z, acc[8]);
    acc[9]  = fmaf(p0, wv.w, acc[9]);
    acc[10] = fmaf(p1, wv.w, acc[10]);
    acc[11] = fmaf(p2, wv.w, acc[11]);
}

// Tiled finalize, node-pair per thread: 64 nodes/block, 256 threads.
// Thread (tp = t/8, tc = t%8) computes nodes {2tp, 2tp+1}.
__global__ void __launch_bounds__(256, 3) k_finalize(
        float* __restrict__ out,
        const float* __restrict__ W0,
        const float* __restrict__ W1,
        const float* __restrict__ gamma,
        const float* __restrict__ beta,
        int N, int E) {
    __shared__ float sA[TILE_N * SAS];
    __shared__ float W0sh[SC][SC];
    __shared__ float W1sh[VC][VC];

    int t  = threadIdx.x;
    int tp = t >> 3;
    int tc = t & 7;
    int base = blockIdx.x * TILE_N;
    int r0 = 2 * tp, r1 = 2 * tp + 1;

    for (int i = t; i < SC * SC; i += 256) W0sh[i >> 6][i & 63] = W0[i];
    for (int i = t; i < VC * VC; i += 256) W1sh[i >> 5][i & 31] = W1[i];

    for (int j = t; j < TILE_N * (DIMF / 4); j += 256) {
        int r  = j / 40;
        int c4 = j - r * 40;
        float4 v = make_float4(0.f, 0.f, 0.f, 0.f);
        int nr = base + r;
        if (nr < N) v = *reinterpret_cast<const float4*>(out + (size_t)nr * DIMF + c4 * 4);
        *reinterpret_cast<float4*>(&sA[r * SAS + c4 * 4]) = v;
    }

    float ew  = (float)(g_ewsum / (double)E);
    float ews = ew * 0.125f;
    float ewv = ew * 0.17677669529663689f;

    __syncthreads();

    // ---- scalar path: 8 accumulators per node ----
    float as0[8], as1[8];
#pragma unroll
    for (int q = 0; q < 8; q++) { as0[q] = 0.f; as1[q] = 0.f; }
#pragma unroll
    for (int k = 0; k < SC; k += 4) {
        float4 a40 = *reinterpret_cast<const float4*>(&sA[r0 * SAS + k]);
        float4 a41 = *reinterpret_cast<const float4*>(&sA[r1 * SAS + k]);
        float av0[4] = {a40.x, a40.y, a40.z, a40.w};
        float av1[4] = {a41.x, a41.y, a41.z, a41.w};
#pragma unroll
        for (int kk = 0; kk < 4; kk++) {
            float4 wl = *reinterpret_cast<const float4*>(&W0sh[k + kk][tc * 4]);
            float4 wh = *reinterpret_cast<const float4*>(&W0sh[k + kk][32 + tc * 4]);
            float a = av0[kk], b = av1[kk];
            as0[0] = fmaf(a, wl.x, as0[0]);  as1[0] = fmaf(b, wl.x, as1[0]);
            as0[1] = fmaf(a, wl.y, as0[1]);  as1[1] = fmaf(b, wl.y, as1[1]);
            as0[2] = fmaf(a, wl.z, as0[2]);  as1[2] = fmaf(b, wl.z, as1[2]);
            as0[3] = fmaf(a, wl.w, as0[3]);  as1[3] = fmaf(b, wl.w, as1[3]);
            as0[4] = fmaf(a, wh.x, as0[4]);  as1[4] = fmaf(b, wh.x, as1[4]);
            as0[5] = fmaf(a, wh.y, as0[5]);  as1[5] = fmaf(b, wh.y, as1[5]);
            as0[6] = fmaf(a, wh.z, as0[6]);  as1[6] = fmaf(b, wh.z, as1[6]);
            as0[7] = fmaf(a, wh.w, as0[7]);  as1[7] = fmaf(b, wh.w, as1[7]);
        }
    }

    // ---- vector path: 12-channel blocks, all-float4 loads ----
    float av0a[12], av1a[12];
#pragma unroll
    for (int q = 0; q < 12; q++) { av0a[q] = 0.f; av1a[q] = 0.f; }
#pragma unroll
    for (int u = 0; u < 8; u++) {
        const float* b0 = &sA[r0 * SAS + SC + 12 * u];
        const float* b1 = &sA[r1 * SAS + SC + 12 * u];
        float4 A0 = *reinterpret_cast<const float4*>(b0);
        float4 B0 = *reinterpret_cast<const float4*>(b0 + 4);
        float4 C0 = *reinterpret_cast<const float4*>(b0 + 8);
        float4 A1 = *reinterpret_cast<const float4*>(b1);
        float4 B1 = *reinterpret_cast<const float4*>(b1 + 4);
        float4 C1 = *reinterpret_cast<const float4*>(b1 + 8);
        float4 w0 = *reinterpret_cast<const float4*>(&W1sh[4*u+0][tc * 4]);
        float4 w1 = *reinterpret_cast<const float4*>(&W1sh[4*u+1][tc * 4]);
        float4 w2 = *reinterpret_cast<const float4*>(&W1sh[4*u+2][tc * 4]);
        float4 w3 = *reinterpret_cast<const float4*>(&W1sh[4*u+3][tc * 4]);
        vacc(av0a, A0.x, A0.y, A0.z, w0);
        vacc(av0a, A0.w, B0.x, B0.y, w1);
        vacc(av0a, B0.z, B0.w, C0.x, w2);
        vacc(av0a, C0.y, C0.z, C0.w, w3);
        vacc(av1a, A1.x, A1.y, A1.z, w0);
        vacc(av1a, A1.w, B1.x, B1.y, w1);
        vacc(av1a, B1.z, B1.w, C1.x, w2);
        vacc(av1a, C1.y, C1.z, C1.w, w3);
    }

    // ---- scale + LN stats (per node) over the 8 tc-lanes ----
    float s10 = 0.f, s20 = 0.f, s11 = 0.f, s21 = 0.f;
#pragma unroll
    for (int q = 0; q < 8; q++) {
        as0[q] *= ews;  s10 += as0[q];  s20 += as0[q] * as0[q];
        as1[q] *= ews;  s11 += as1[q];  s21 += as1[q] * as1[q];
    }
#pragma unroll
    for (int o = 1; o < 8; o <<= 1) {
        s10 += __shfl_xor_sync(0xffffffffu, s10, o);
        s20 += __shfl_xor_sync(0xffffffffu, s20, o);
        s11 += __shfl_xor_sync(0xffffffffu, s11, o);
        s21 += __shfl_xor_sync(0xffffffffu, s21, o);
    }
    float mu0  = s10 * (1.0f / SC);
    float var0 = s20 * (1.0f / SC) - mu0 * mu0;
    float rs0  = rsqrtf(var0 + 1e-5f);
    float mu1  = s11 * (1.0f / SC);
    float var1 = s21 * (1.0f / SC) - mu1 * mu1;
    float rs1  = rsqrtf(var1 + 1e-5f);

    float4 gl = *reinterpret_cast<const float4*>(gamma + tc * 4);
    float4 gh = *reinterpret_cast<const float4*>(gamma + 32 + tc * 4);
    float4 bl = *reinterpret_cast<const float4*>(beta + tc * 4);
    float4 bh = *reinterpret_cast<const float4*>(beta + 32 + tc * 4);
    float gvv[8] = {gl.x, gl.y, gl.z, gl.w, gh.x, gh.y, gh.z, gh.w};
    float bvv[8] = {bl.x, bl.y, bl.z, bl.w, bh.x, bh.y, bh.z, bh.w};

#pragma unroll
    for (int nn = 0; nn < 2; nn++) {
        int n = base + 2 * tp + nn;
        if (n >= N) break;
        float mu = nn ? mu1 : mu0;
        float rs = nn ? rs1 : rs0;
        float* asv = nn ? as1 : as0;
        float* avv = nn ? av1a : av0a;
        float* orow = out + (size_t)n * DIMF;
        float o8[8];
#pragma unroll
        for (int q = 0; q < 8; q++) {
            float xln = (asv[q] - mu) * rs * gvv[q] + bvv[q];
            o8[q] = xln / (1.f + expf(-xln));
        }
        *reinterpret_cast<float4*>(orow + tc * 4) =
            make_float4(o8[0], o8[1], o8[2], o8[3]);
        *reinterpret_cast<float4*>(orow + 32 + tc * 4) =
            make_float4(o8[4], o8[5], o8[6], o8[7]);
        float* ov = orow + SC + tc * 12;
        *reinterpret_cast<float4*>(ov + 0) =
            make_float4(avv[0] * ewv, avv[1] * ewv, avv[2] * ewv, avv[3] * ewv);
        *reinterpret_cast<float4*>(ov + 4) =
            make_float4(avv[4] * ewv, avv[5] * ewv, avv[6] * ewv, avv[7] * ewv);
        *reinterpret_cast<float4*>(ov + 8) =
            make_float4(avv[8] * ewv, avv[9] * ewv, avv[10] * ewv, avv[11] * ewv);
    }
}

extern "C" void kernel_launch(void* const* d_in, const int* in_sizes, int n_in,
                              void* d_out, int out_size) {
    const float* x       = (const float*)d_in[0];
    const float* pos     = (const float*)d_in[1];
    const int*   ei      = (const int*)d_in[2];   // int32 (JAX x64 disabled)
    // d_in[3] = edge_rand: unused (rotation cancels algebraically)
    const float* W0      = (const float*)d_in[4];
    const float* W1      = (const float*)d_in[5];
    const float* centers = (const float*)d_in[6];
    const float* widths  = (const float*)d_in[7];
    const float* pw      = (const float*)d_in[8];
    const float* pb      = (const float*)d_in[9];
    const float* gamma   = (const float*)d_in[10];
    const float* beta    = (const float*)d_in[11];
    float* out = (float*)d_out;

    int N = in_sizes[0] / DIMF;
    int E = in_sizes[2] / 2;
    int nq = (N * DIMF) / 4;

    k_table_zero<<<2560, 256>>>(centers, widths, pw, pb, (float4*)out, nq);
    k_scatter<<<(E + 31) / 32, 256>>>(ei, x, pos, out, E);
    k_finalize<<<(N + TILE_N - 1) / TILE_N, 256>>>(out, W0, W1, gamma, beta, N, E);
}